// round 9
// baseline (speedup 1.0000x reference)
#include <cuda_runtime.h>
#include <cuda_fp16.h>

// Problem constants
#define NROWS 32768
#define INF   512
#define HIDF  2048
#define OUTF  512

#define NSTAGE 3
#define STAGE_BYTES 49152u          // A 32KB (256 rows) + B 16KB (128 rows), f16 Kchunk=64
#define DYN_SMEM (NSTAGE * STAGE_BYTES)

// ---------------- device scratch (no allocations allowed) ----------------
__device__ unsigned short g_W1s[HIDF * INF];           // sign(W1) f16 +-1
__device__ unsigned short g_W2s[(size_t)HIDF * HIDF];
__device__ unsigned short g_W3s[OUTF * HIDF];
__device__ float g_alpha1[HIDF];
__device__ float g_alpha2[HIDF];
__device__ float g_alpha3[OUTF];
__device__ unsigned short g_xs[(size_t)NROWS * INF];   // sign(x)
__device__ unsigned short g_h1[(size_t)NROWS * HIDF];
__device__ unsigned short g_h2[(size_t)NROWS * HIDF];
__device__ float g_beta0[NROWS];
__device__ float g_beta1[NROWS];
__device__ float g_beta2[NROWS];
__device__ float g_part1[NROWS * 16];
__device__ float g_part2[NROWS * 16];

#define PH 0x3C00u   // +1.0 f16
#define NH 0xBC00u   // -1.0 f16

// ---------------- weight prep: alpha = mean|W| per row; sign(W) -> f16 ----------------
__global__ void prepw_kernel(const float* __restrict__ W, unsigned short* __restrict__ Ws,
                             float* __restrict__ alpha, int C)
{
    int r = blockIdx.x;
    int tid = threadIdx.x;
    float s = 0.f;
    for (int c = tid; c < C; c += 256) {
        float w = W[(size_t)r * C + c];
        s += fabsf(w);
        Ws[(size_t)r * C + c] = (w >= 0.f) ? PH : NH;
    }
    #pragma unroll
    for (int off = 16; off; off >>= 1) s += __shfl_xor_sync(0xffffffffu, s, off);
    __shared__ float sw[8];
    if ((tid & 31) == 0) sw[tid >> 5] = s;
    __syncthreads();
    if (tid == 0) {
        float t = 0.f;
        #pragma unroll
        for (int i = 0; i < 8; i++) t += sw[i];
        alpha[r] = t * (1.f / C);
    }
}

// ---------------- binarize x -> f16 signs, beta0 = mean|x| (one warp per row) ----------------
__global__ void binx_kernel(const float* __restrict__ x, unsigned short* __restrict__ xs,
                            float* __restrict__ beta0)
{
    int warp = (blockIdx.x * blockDim.x + threadIdx.x) >> 5;
    int lane = threadIdx.x & 31;
    const float4* xr = (const float4*)(x + (size_t)warp * INF);
    float s = 0.f;
    #pragma unroll
    for (int k2 = 0; k2 < 4; k2++) {
        float4 v = xr[lane + k2 * 32];
        s += fabsf(v.x) + fabsf(v.y) + fabsf(v.z) + fabsf(v.w);
        unsigned p0 = (v.x >= 0.f ? PH : NH) | ((v.y >= 0.f ? PH : NH) << 16);
        unsigned p1 = (v.z >= 0.f ? PH : NH) | ((v.w >= 0.f ? PH : NH) << 16);
        *(uint2*)(xs + (size_t)warp * INF + (size_t)(lane + k2 * 32) * 4) = make_uint2(p0, p1);
    }
    #pragma unroll
    for (int off = 16; off; off >>= 1) s += __shfl_xor_sync(0xffffffffu, s, off);
    if (lane == 0) beta0[warp] = s * (1.f / INF);
}

// ---------------- beta from deterministic partials ----------------
__global__ void redbeta_kernel(const float* __restrict__ part, float* __restrict__ beta,
                               int nb, float inv)
{
    int r = blockIdx.x * blockDim.x + threadIdx.x;
    float s = 0.f;
    for (int i = 0; i < nb; i++) s += part[(size_t)r * nb + i];
    beta[r] = s * inv;
}

// ---------------- main GEMM: C[256x128] = A(f16 ±1) @ B(f16 ±1)^T, f16 accum (exact) ----------------
// 8 warps as 4(m) x 2(n); warp tile 64x64 via m16n8k16.f16 (f16 acc: all partial sums
// are integers <= 2048 = 2^11, exactly representable -> bit-exact vs f32 accumulation).
// 3-stage ring, one __syncthreads per K-chunk (R8-verified safe schedule).

__device__ __forceinline__ unsigned swz(unsigned row, unsigned chunk)
{
    return row * 128u + ((chunk ^ (row & 7u)) << 4);
}

template <bool FINAL>
__global__ void __launch_bounds__(256)
bingemm_kernel(const unsigned short* __restrict__ A, const unsigned short* __restrict__ B,
               const float* __restrict__ beta, const float* __restrict__ alpha,
               const float* __restrict__ bias, const float* __restrict__ prelu_w,
               unsigned short* __restrict__ signOut, float* __restrict__ absPart,
               float* __restrict__ outF, int Nn, int K)
{
    extern __shared__ __align__(16) unsigned char smem[];
    const int tid = threadIdx.x;
    const int lane = tid & 31, warp = tid >> 5;
    const int wm = warp >> 1, wn = warp & 1;        // 4 x 2
    const int bm = blockIdx.y, bn = blockIdx.x;
    const int nb = gridDim.x;

    unsigned sbase = (unsigned)__cvta_generic_to_shared(smem);

    __shared__ float s_beta[256], s_alpha[128], s_bias[128];
    __shared__ float s_red[256][2];

    s_beta[tid] = beta[bm * 256 + tid];             // all 256 threads
    if (tid < 128) {
        s_alpha[tid] = alpha[bn * 128 + tid];
        s_bias[tid]  = bias[bn * 128 + tid];
    }

    const int KT = K / 64;
    const unsigned short* Ag = A + (size_t)(bm * 256) * K;
    const unsigned short* Bg = B + (size_t)(bn * 128) * K;

    auto load_tile = [&](int kt, int stage) {
        unsigned sA = sbase + (unsigned)stage * STAGE_BYTES;
        unsigned sB = sA + 32768u;
        #pragma unroll
        for (int it = 0; it < 8; it++) {            // A: 256 rows x 128B
            int id = it * 256 + tid;
            int row = id >> 3, ch = id & 7;
            const void* gA = Ag + (size_t)row * K + kt * 64 + ch * 8;
            unsigned dA = sA + swz((unsigned)row, (unsigned)ch);
            asm volatile("cp.async.cg.shared.global [%0], [%1], 16;\n" :: "r"(dA), "l"(gA) : "memory");
        }
        #pragma unroll
        for (int it = 0; it < 4; it++) {            // B: 128 rows x 128B
            int id = it * 256 + tid;
            int row = id >> 3, ch = id & 7;
            const void* gB = Bg + (size_t)row * K + kt * 64 + ch * 8;
            unsigned dB = sB + swz((unsigned)row, (unsigned)ch);
            asm volatile("cp.async.cg.shared.global [%0], [%1], 16;\n" :: "r"(dB), "l"(gB) : "memory");
        }
        asm volatile("cp.async.commit_group;\n" ::: "memory");
    };

    unsigned acc[4][8][2];                          // f16x2 accumulators, 64 regs
    #pragma unroll
    for (int i = 0; i < 4; i++)
        #pragma unroll
        for (int j = 0; j < 8; j++) { acc[i][j][0] = 0u; acc[i][j][1] = 0u; }

    load_tile(0, 0);
    load_tile(1, 1);

    int slot = 0;
    for (int kt = 0; kt < KT; kt++) {
        if (kt + 1 < KT) asm volatile("cp.async.wait_group 1;\n" ::: "memory");
        else             asm volatile("cp.async.wait_group 0;\n" ::: "memory");
        __syncthreads();

        if (kt + 2 < KT) {
            int ps = slot + 2; if (ps >= NSTAGE) ps -= NSTAGE;
            load_tile(kt + 2, ps);
        }

        unsigned sA = sbase + (unsigned)slot * STAGE_BYTES;
        unsigned sB = sA + 32768u;

        #pragma unroll
        for (int ks = 0; ks < 4; ks++) {
            unsigned a[4][4];
            #pragma unroll
            for (int i = 0; i < 4; i++) {
                unsigned row = (unsigned)(wm * 64 + i * 16 + (lane & 15));
                unsigned ch  = (unsigned)(2 * ks + (lane >> 4));
                unsigned addr = sA + swz(row, ch);
                asm volatile("ldmatrix.sync.aligned.m8n8.x4.shared.b16 {%0,%1,%2,%3}, [%4];\n"
                             : "=r"(a[i][0]), "=r"(a[i][1]), "=r"(a[i][2]), "=r"(a[i][3])
                             : "r"(addr));
            }
            unsigned b[8][2];
            #pragma unroll
            for (int j = 0; j < 8; j += 2) {
                unsigned row = (unsigned)(wn * 64 + j * 8 + ((lane >> 4) << 3) + (lane & 7));
                unsigned ch  = (unsigned)(2 * ks + ((lane >> 3) & 1));
                unsigned addr = sB + swz(row, ch);
                asm volatile("ldmatrix.sync.aligned.m8n8.x4.shared.b16 {%0,%1,%2,%3}, [%4];\n"
                             : "=r"(b[j][0]), "=r"(b[j][1]), "=r"(b[j + 1][0]), "=r"(b[j + 1][1])
                             : "r"(addr));
            }
            #pragma unroll
            for (int i = 0; i < 4; i++)
                #pragma unroll
                for (int j = 0; j < 8; j++) {
                    asm volatile(
                        "mma.sync.aligned.m16n8k16.row.col.f16.f16.f16.f16 "
                        "{%0,%1}, {%2,%3,%4,%5}, {%6,%7}, {%0,%1};\n"
                        : "+r"(acc[i][j][0]), "+r"(acc[i][j][1])
                        : "r"(a[i][0]), "r"(a[i][1]), "r"(a[i][2]), "r"(a[i][3]),
                          "r"(b[j][0]), "r"(b[j][1]));
                }
        }
        if (++slot == NSTAGE) slot = 0;
    }
    __syncthreads();

    // ---------------- fused epilogue (f16 acc -> exact f32, same op order) ----------------
    const int g = lane >> 2, t = lane & 3;
    float pa = 0.f;
    if (!FINAL) pa = prelu_w[0];

    #pragma unroll
    for (int i = 0; i < 4; i++) {
        int r0l = wm * 64 + i * 16 + g;
        int r1l = r0l + 8;
        float be0 = s_beta[r0l], be1 = s_beta[r1l];
        float rs0 = 0.f, rs1 = 0.f;
        #pragma unroll
        for (int j = 0; j < 8; j++) {
            int cl = wn * 64 + j * 8 + 2 * t;
            float al0 = s_alpha[cl], al1 = s_alpha[cl + 1];
            float bi0 = s_bias[cl],  bi1 = s_bias[cl + 1];
            float2 f0 = __half22float2(*(__half2*)&acc[i][j][0]);  // row r0: cols cl, cl+1
            float2 f1 = __half22float2(*(__half2*)&acc[i][j][1]);  // row r1
            // match reference op order: ((y*beta)*alpha) + b   (y exact integer)
            float v00 = (f0.x * be0) * al0 + bi0;
            float v01 = (f0.y * be0) * al1 + bi1;
            float v10 = (f1.x * be1) * al0 + bi0;
            float v11 = (f1.y * be1) * al1 + bi1;
            size_t r0 = (size_t)(bm * 256 + r0l);
            size_t r1 = (size_t)(bm * 256 + r1l);
            int c = bn * 128 + cl;
            if (FINAL) {
                *(float2*)(outF + r0 * Nn + c) = make_float2(v00, v01);
                *(float2*)(outF + r1 * Nn + c) = make_float2(v10, v11);
            } else {
                float p00 = v00 > 0.f ? v00 : pa * v00;
                float p01 = v01 > 0.f ? v01 : pa * v01;
                float p10 = v10 > 0.f ? v10 : pa * v10;
                float p11 = v11 > 0.f ? v11 : pa * v11;
                rs0 += fabsf(p00) + fabsf(p01);
                rs1 += fabsf(p10) + fabsf(p11);
                // sign(prelu(v)) == (v >= 0 ? +1 : -1)  (pa > 0, sign(0) -> +1)
                unsigned s0 = (v00 >= 0.f ? PH : NH) | ((v01 >= 0.f ? PH : NH) << 16);
                unsigned s1 = (v10 >= 0.f ? PH : NH) | ((v11 >= 0.f ? PH : NH) << 16);
                *(unsigned*)(signOut + r0 * Nn + c) = s0;
                *(unsigned*)(signOut + r1 * Nn + c) = s1;
            }
        }
        if (!FINAL) {
            rs0 += __shfl_xor_sync(0xffffffffu, rs0, 1);
            rs0 += __shfl_xor_sync(0xffffffffu, rs0, 2);
            rs1 += __shfl_xor_sync(0xffffffffu, rs1, 1);
            rs1 += __shfl_xor_sync(0xffffffffu, rs1, 2);
            if (t == 0) { s_red[r0l][wn] = rs0; s_red[r1l][wn] = rs1; }
        }
    }
    if (!FINAL) {
        __syncthreads();
        // one writer per (row, nblock): deterministic
        absPart[(size_t)(bm * 256 + tid) * nb + bn] = s_red[tid][0] + s_red[tid][1];
    }
}

// ---------------- launch ----------------
extern "C" void kernel_launch(void* const* d_in, const int* in_sizes, int n_in,
                              void* d_out, int out_size)
{
    const float* x  = (const float*)d_in[0];
    const float* W1 = (const float*)d_in[1];
    const float* b1 = (const float*)d_in[2];
    const float* W2 = (const float*)d_in[3];
    const float* b2 = (const float*)d_in[4];
    const float* W3 = (const float*)d_in[5];
    const float* b3 = (const float*)d_in[6];
    const float* pw = (const float*)d_in[7];
    float* out = (float*)d_out;

    cudaFuncSetAttribute(bingemm_kernel<false>, cudaFuncAttributeMaxDynamicSharedMemorySize, DYN_SMEM);
    cudaFuncSetAttribute(bingemm_kernel<true>,  cudaFuncAttributeMaxDynamicSharedMemorySize, DYN_SMEM);

    void *pW1s, *pW2s, *pW3s, *pa1, *pa2, *pa3, *pxs, *ph1, *ph2;
    void *pbe0, *pbe1, *pbe2, *pp1, *pp2;
    cudaGetSymbolAddress(&pW1s, g_W1s);
    cudaGetSymbolAddress(&pW2s, g_W2s);
    cudaGetSymbolAddress(&pW3s, g_W3s);
    cudaGetSymbolAddress(&pa1, g_alpha1);
    cudaGetSymbolAddress(&pa2, g_alpha2);
    cudaGetSymbolAddress(&pa3, g_alpha3);
    cudaGetSymbolAddress(&pxs, g_xs);
    cudaGetSymbolAddress(&ph1, g_h1);
    cudaGetSymbolAddress(&ph2, g_h2);
    cudaGetSymbolAddress(&pbe0, g_beta0);
    cudaGetSymbolAddress(&pbe1, g_beta1);
    cudaGetSymbolAddress(&pbe2, g_beta2);
    cudaGetSymbolAddress(&pp1, g_part1);
    cudaGetSymbolAddress(&pp2, g_part2);

    // weight prep
    prepw_kernel<<<HIDF, 256>>>(W1, (unsigned short*)pW1s, (float*)pa1, INF);
    prepw_kernel<<<HIDF, 256>>>(W2, (unsigned short*)pW2s, (float*)pa2, HIDF);
    prepw_kernel<<<OUTF, 256>>>(W3, (unsigned short*)pW3s, (float*)pa3, HIDF);
    // binarize input + beta0
    binx_kernel<<<NROWS / 8, 256>>>(x, (unsigned short*)pxs, (float*)pbe0);

    // layer 1: [N,512] -> [N,2048]
    bingemm_kernel<false><<<dim3(HIDF / 128, NROWS / 256), 256, DYN_SMEM>>>(
        (const unsigned short*)pxs, (const unsigned short*)pW1s,
        (const float*)pbe0, (const float*)pa1, b1, pw,
        (unsigned short*)ph1, (float*)pp1, nullptr, HIDF, INF);
    redbeta_kernel<<<NROWS / 256, 256>>>((const float*)pp1, (float*)pbe1, HIDF / 128, 1.f / HIDF);

    // layer 2: [N,2048] -> [N,2048]
    bingemm_kernel<false><<<dim3(HIDF / 128, NROWS / 256), 256, DYN_SMEM>>>(
        (const unsigned short*)ph1, (const unsigned short*)pW2s,
        (const float*)pbe1, (const float*)pa2, b2, pw,
        (unsigned short*)ph2, (float*)pp2, nullptr, HIDF, HIDF);
    redbeta_kernel<<<NROWS / 256, 256>>>((const float*)pp2, (float*)pbe2, HIDF / 128, 1.f / HIDF);

    // layer 3: [N,2048] -> [N,512], no activation, write fp32 to d_out
    bingemm_kernel<true><<<dim3(OUTF / 128, NROWS / 256), 256, DYN_SMEM>>>(
        (const unsigned short*)ph2, (const unsigned short*)pW3s,
        (const float*)pbe2, (const float*)pa3, b3, pw,
        nullptr, nullptr, out, OUTF, HIDF);
}

// round 12
// speedup vs baseline: 1.1494x; 1.1494x over previous
#include <cuda_runtime.h>
#include <cuda_bf16.h>

// Problem constants
#define NROWS 32768
#define INF   512
#define HIDF  2048
#define OUTF  512

#define NSTAGE 3
#define STAGE_BYTES 32768u          // A 16KB + B 16KB per stage (bf16, Kchunk=64)
#define DYN_SMEM (NSTAGE * STAGE_BYTES)

// ---------------- device scratch (no allocations allowed) ----------------
__device__ __nv_bfloat16 g_W1s[HIDF * INF];     // sign(W1) bf16
__device__ __nv_bfloat16 g_W2s[(size_t)HIDF * HIDF];
__device__ __nv_bfloat16 g_W3s[OUTF * HIDF];
__device__ float g_alpha1[HIDF];
__device__ float g_alpha2[HIDF];
__device__ float g_alpha3[OUTF];
__device__ __nv_bfloat16 g_xs[(size_t)NROWS * INF];
__device__ __nv_bfloat16 g_h1[(size_t)NROWS * HIDF];
__device__ __nv_bfloat16 g_h2[(size_t)NROWS * HIDF];
__device__ float g_beta0[NROWS];
__device__ float g_beta1[NROWS];
__device__ float g_beta2[NROWS];
__device__ float g_part1[NROWS * 16];
__device__ float g_part2[NROWS * 16];

// ---------------- weight prep: alpha = mean|W| per row; sign(W) -> bf16 ----------------
__global__ void prepw_kernel(const float* __restrict__ W, __nv_bfloat16* __restrict__ Ws,
                             float* __restrict__ alpha, int C)
{
    int r = blockIdx.x;
    int tid = threadIdx.x;
    float s = 0.f;
    for (int c = tid; c < C; c += 256) {
        float w = W[(size_t)r * C + c];
        s += fabsf(w);
        Ws[(size_t)r * C + c] = __float2bfloat16(w >= 0.f ? 1.f : -1.f);
    }
    #pragma unroll
    for (int off = 16; off; off >>= 1) s += __shfl_xor_sync(0xffffffffu, s, off);
    __shared__ float sw[8];
    if ((tid & 31) == 0) sw[tid >> 5] = s;
    __syncthreads();
    if (tid == 0) {
        float t = 0.f;
        #pragma unroll
        for (int i = 0; i < 8; i++) t += sw[i];
        alpha[r] = t * (1.f / C);
    }
}

// ---------------- binarize x, beta0 = mean|x| per row (one warp per row) ----------------
__global__ void binx_kernel(const float* __restrict__ x, __nv_bfloat16* __restrict__ xs,
                            float* __restrict__ beta0)
{
    int warp = (blockIdx.x * blockDim.x + threadIdx.x) >> 5;
    int lane = threadIdx.x & 31;
    const float4* xr = (const float4*)(x + (size_t)warp * INF);
    float s = 0.f;
    #pragma unroll
    for (int k2 = 0; k2 < 4; k2++) {
        float4 v = xr[lane + k2 * 32];
        s += fabsf(v.x) + fabsf(v.y) + fabsf(v.z) + fabsf(v.w);
        unsigned p0 = (v.x >= 0.f ? 0x3F80u : 0xBF80u) | ((v.y >= 0.f ? 0x3F80u : 0xBF80u) << 16);
        unsigned p1 = (v.z >= 0.f ? 0x3F80u : 0xBF80u) | ((v.w >= 0.f ? 0x3F80u : 0xBF80u) << 16);
        *(uint2*)(xs + (size_t)warp * INF + (size_t)(lane + k2 * 32) * 4) = make_uint2(p0, p1);
    }
    #pragma unroll
    for (int off = 16; off; off >>= 1) s += __shfl_xor_sync(0xffffffffu, s, off);
    if (lane == 0) beta0[warp] = s * (1.f / INF);
}

// ---------------- beta from deterministic partials ----------------
__global__ void redbeta_kernel(const float* __restrict__ part, float* __restrict__ beta,
                               int nb, float inv)
{
    int r = blockIdx.x * blockDim.x + threadIdx.x;
    float s = 0.f;
    for (int i = 0; i < nb; i++) s += part[(size_t)r * nb + i];
    beta[r] = s * inv;
}

// ---------------- main GEMM: C = A(bf16 ±1) @ B(bf16 ±1)^T, 3-stage ring ----------------
// Tile 128x128x64, 256 threads (8 warps as 4x2), warp tile 32x64 via m16n8k16.
// A-fragment pipeline: ldmatrix for k-step ks+1 issued before the HMMAs of ks.
// Plain __launch_bounds__(256): occupancy left to HW (2 CTAs/SM fit naturally).

__device__ __forceinline__ unsigned swz(unsigned row, unsigned chunk)
{
    return row * 128u + ((chunk ^ (row & 7u)) << 4);
}

template <bool FINAL>
__global__ void __launch_bounds__(256)
bingemm_kernel(const __nv_bfloat16* __restrict__ A, const __nv_bfloat16* __restrict__ B,
               const float* __restrict__ beta, const float* __restrict__ alpha,
               const float* __restrict__ bias, const float* __restrict__ prelu_w,
               __nv_bfloat16* __restrict__ signOut, float* __restrict__ absPart,
               float* __restrict__ outF, int Nn, int K)
{
    extern __shared__ __align__(16) unsigned char smem[];
    const int tid = threadIdx.x;
    const int lane = tid & 31, warp = tid >> 5;
    const int wm = warp >> 1, wn = warp & 1;
    const int bm = blockIdx.y, bn = blockIdx.x;
    const int nb = gridDim.x;

    unsigned sbase = (unsigned)__cvta_generic_to_shared(smem);

    __shared__ float s_beta[128], s_alpha[128], s_bias[128];
    __shared__ float s_red[128][2];

    if (tid < 128) {
        s_beta[tid]  = beta[bm * 128 + tid];
        s_alpha[tid] = alpha[bn * 128 + tid];
        s_bias[tid]  = bias[bn * 128 + tid];
    }

    const int KT = K / 64;
    const __nv_bfloat16* Ag = A + (size_t)(bm * 128) * K;
    const __nv_bfloat16* Bg = B + (size_t)(bn * 128) * K;

    auto load_tile = [&](int kt, int stage) {
        unsigned sA = sbase + (unsigned)stage * STAGE_BYTES;
        unsigned sB = sA + 16384u;
        #pragma unroll
        for (int it = 0; it < 4; it++) {
            int id = it * 256 + tid;
            int row = id >> 3, ch = id & 7;
            const void* gA = Ag + (size_t)row * K + kt * 64 + ch * 8;
            unsigned dA = sA + swz((unsigned)row, (unsigned)ch);
            asm volatile("cp.async.cg.shared.global [%0], [%1], 16;\n" :: "r"(dA), "l"(gA) : "memory");
            const void* gB = Bg + (size_t)row * K + kt * 64 + ch * 8;
            unsigned dB = sB + swz((unsigned)row, (unsigned)ch);
            asm volatile("cp.async.cg.shared.global [%0], [%1], 16;\n" :: "r"(dB), "l"(gB) : "memory");
        }
        asm volatile("cp.async.commit_group;\n" ::: "memory");
    };

    // per-warp A-ldmatrix addressing (row fixed; chunk varies with ks)
    const unsigned a_row0 = (unsigned)(wm * 32 + (lane & 15));
    const unsigned a_chbase = (unsigned)(lane >> 4);

    auto ldA = [&](unsigned sA, int ks, unsigned (&a)[2][4]) {
        #pragma unroll
        for (int i = 0; i < 2; i++) {
            unsigned addr = sA + swz(a_row0 + i * 16, (unsigned)(2 * ks) + a_chbase);
            asm volatile("ldmatrix.sync.aligned.m8n8.x4.shared.b16 {%0,%1,%2,%3}, [%4];\n"
                         : "=r"(a[i][0]), "=r"(a[i][1]), "=r"(a[i][2]), "=r"(a[i][3])
                         : "r"(addr));
        }
    };

    float acc[2][8][4];
    #pragma unroll
    for (int i = 0; i < 2; i++)
        #pragma unroll
        for (int j = 0; j < 8; j++)
            #pragma unroll
            for (int q = 0; q < 4; q++) acc[i][j][q] = 0.f;

    load_tile(0, 0);
    load_tile(1, 1);

    int slot = 0;
    for (int kt = 0; kt < KT; kt++) {
        if (kt + 1 < KT) asm volatile("cp.async.wait_group 1;\n" ::: "memory");
        else             asm volatile("cp.async.wait_group 0;\n" ::: "memory");
        __syncthreads();

        if (kt + 2 < KT) {
            int ps = slot + 2; if (ps >= NSTAGE) ps -= NSTAGE;
            load_tile(kt + 2, ps);
        }

        unsigned sA = sbase + (unsigned)slot * STAGE_BYTES;
        unsigned sB = sA + 16384u;

        unsigned abuf[2][2][4];          // double-buffered A fragments
        ldA(sA, 0, abuf[0]);

        #pragma unroll
        for (int ks = 0; ks < 4; ks++) {
            if (ks < 3) ldA(sA, ks + 1, abuf[(ks + 1) & 1]);   // prefetch next A
            unsigned (&a)[2][4] = abuf[ks & 1];

            unsigned b[8][2];
            #pragma unroll
            for (int j = 0; j < 8; j += 2) {
                unsigned row = (unsigned)(wn * 64 + j * 8 + ((lane >> 4) << 3) + (lane & 7));
                unsigned ch  = (unsigned)(2 * ks + ((lane >> 3) & 1));
                unsigned addr = sB + swz(row, ch);
                asm volatile("ldmatrix.sync.aligned.m8n8.x4.shared.b16 {%0,%1,%2,%3}, [%4];\n"
                             : "=r"(b[j][0]), "=r"(b[j][1]), "=r"(b[j + 1][0]), "=r"(b[j + 1][1])
                             : "r"(addr));
            }
            #pragma unroll
            for (int i = 0; i < 2; i++)
                #pragma unroll
                for (int j = 0; j < 8; j++) {
                    asm volatile(
                        "mma.sync.aligned.m16n8k16.row.col.f32.bf16.bf16.f32 "
                        "{%0,%1,%2,%3}, {%4,%5,%6,%7}, {%8,%9}, {%0,%1,%2,%3};\n"
                        : "+f"(acc[i][j][0]), "+f"(acc[i][j][1]), "+f"(acc[i][j][2]), "+f"(acc[i][j][3])
                        : "r"(a[i][0]), "r"(a[i][1]), "r"(a[i][2]), "r"(a[i][3]),
                          "r"(b[j][0]), "r"(b[j][1]));
                }
        }
        if (++slot == NSTAGE) slot = 0;
    }
    __syncthreads();

    // ---------------- fused epilogue (identical arithmetic to passing R1/R8) ----------------
    const int g = lane >> 2, t = lane & 3;
    float pa = 0.f;
    if (!FINAL) pa = prelu_w[0];

    #pragma unroll
    for (int i = 0; i < 2; i++) {
        int r0l = wm * 32 + i * 16 + g;
        int r1l = r0l + 8;
        float be0 = s_beta[r0l], be1 = s_beta[r1l];
        float rs0 = 0.f, rs1 = 0.f;
        #pragma unroll
        for (int j = 0; j < 8; j++) {
            int cl = wn * 64 + j * 8 + 2 * t;
            float al0 = s_alpha[cl], al1 = s_alpha[cl + 1];
            float bi0 = s_bias[cl],  bi1 = s_bias[cl + 1];
            float v00 = (acc[i][j][0] * be0) * al0 + bi0;
            float v01 = (acc[i][j][1] * be0) * al1 + bi1;
            float v10 = (acc[i][j][2] * be1) * al0 + bi0;
            float v11 = (acc[i][j][3] * be1) * al1 + bi1;
            size_t r0 = (size_t)(bm * 128 + r0l);
            size_t r1 = (size_t)(bm * 128 + r1l);
            int c = bn * 128 + cl;
            if (FINAL) {
                *(float2*)(outF + r0 * Nn + c) = make_float2(v00, v01);
                *(float2*)(outF + r1 * Nn + c) = make_float2(v10, v11);
            } else {
                float p00 = v00 > 0.f ? v00 : pa * v00;
                float p01 = v01 > 0.f ? v01 : pa * v01;
                float p10 = v10 > 0.f ? v10 : pa * v10;
                float p11 = v11 > 0.f ? v11 : pa * v11;
                rs0 += fabsf(p00) + fabsf(p01);
                rs1 += fabsf(p10) + fabsf(p11);
                // sign(prelu(v)) == (v >= 0 ? +1 : -1)  (pa > 0, sign(0) -> +1)
                unsigned s0 = (v00 >= 0.f ? 0x3F80u : 0xBF80u) | ((v01 >= 0.f ? 0x3F80u : 0xBF80u) << 16);
                unsigned s1 = (v10 >= 0.f ? 0x3F80u : 0xBF80u) | ((v11 >= 0.f ? 0x3F80u : 0xBF80u) << 16);
                *(unsigned*)(signOut + r0 * Nn + c) = s0;
                *(unsigned*)(signOut + r1 * Nn + c) = s1;
            }
        }
        if (!FINAL) {
            rs0 += __shfl_xor_sync(0xffffffffu, rs0, 1);
            rs0 += __shfl_xor_sync(0xffffffffu, rs0, 2);
            rs1 += __shfl_xor_sync(0xffffffffu, rs1, 1);
            rs1 += __shfl_xor_sync(0xffffffffu, rs1, 2);
            if (t == 0) { s_red[r0l][wn] = rs0; s_red[r1l][wn] = rs1; }
        }
    }
    if (!FINAL) {
        __syncthreads();
        if (tid < 128) {
            // exactly one writer per (row, nblock): fully deterministic
            absPart[(size_t)(bm * 128 + tid) * nb + bn] = s_red[tid][0] + s_red[tid][1];
        }
    }
}

// ---------------- launch ----------------
// Order chosen so GEMM1 lands at our launch index 3 (ncu -s 5 window):
// prepw1, binx, prepw2, GEMM1, redbeta1, prepw3, gemm2, redbeta2, gemm3.
extern "C" void kernel_launch(void* const* d_in, const int* in_sizes, int n_in,
                              void* d_out, int out_size)
{
    const float* x  = (const float*)d_in[0];
    const float* W1 = (const float*)d_in[1];
    const float* b1 = (const float*)d_in[2];
    const float* W2 = (const float*)d_in[3];
    const float* b2 = (const float*)d_in[4];
    const float* W3 = (const float*)d_in[5];
    const float* b3 = (const float*)d_in[6];
    const float* pw = (const float*)d_in[7];
    float* out = (float*)d_out;

    cudaFuncSetAttribute(bingemm_kernel<false>, cudaFuncAttributeMaxDynamicSharedMemorySize, DYN_SMEM);
    cudaFuncSetAttribute(bingemm_kernel<true>,  cudaFuncAttributeMaxDynamicSharedMemorySize, DYN_SMEM);

    void *pW1s, *pW2s, *pW3s, *pa1, *pa2, *pa3, *pxs, *ph1, *ph2;
    void *pbe0, *pbe1, *pbe2, *pp1, *pp2;
    cudaGetSymbolAddress(&pW1s, g_W1s);
    cudaGetSymbolAddress(&pW2s, g_W2s);
    cudaGetSymbolAddress(&pW3s, g_W3s);
    cudaGetSymbolAddress(&pa1, g_alpha1);
    cudaGetSymbolAddress(&pa2, g_alpha2);
    cudaGetSymbolAddress(&pa3, g_alpha3);
    cudaGetSymbolAddress(&pxs, g_xs);
    cudaGetSymbolAddress(&ph1, g_h1);
    cudaGetSymbolAddress(&ph2, g_h2);
    cudaGetSymbolAddress(&pbe0, g_beta0);
    cudaGetSymbolAddress(&pbe1, g_beta1);
    cudaGetSymbolAddress(&pbe2, g_beta2);
    cudaGetSymbolAddress(&pp1, g_part1);
    cudaGetSymbolAddress(&pp2, g_part2);

    // 0: W1 prep
    prepw_kernel<<<HIDF, 256>>>(W1, (__nv_bfloat16*)pW1s, (float*)pa1, INF);
    // 1: binarize input + beta0
    binx_kernel<<<NROWS / 8, 256>>>(x, (__nv_bfloat16*)pxs, (float*)pbe0);
    // 2: W2 prep (independent; positions GEMM1 at index 3)
    prepw_kernel<<<HIDF, 256>>>(W2, (__nv_bfloat16*)pW2s, (float*)pa2, HIDF);
    // 3: layer 1 GEMM  [N,512] -> [N,2048]   <- ncu capture target
    bingemm_kernel<false><<<dim3(HIDF / 128, NROWS / 128), 256, DYN_SMEM>>>(
        (const __nv_bfloat16*)pxs, (const __nv_bfloat16*)pW1s,
        (const float*)pbe0, (const float*)pa1, b1, pw,
        (__nv_bfloat16*)ph1, (float*)pp1, nullptr, HIDF, INF);
    // 4: beta1
    redbeta_kernel<<<NROWS / 256, 256>>>((const float*)pp1, (float*)pbe1, HIDF / 128, 1.f / HIDF);
    // 5: W3 prep
    prepw_kernel<<<OUTF, 256>>>(W3, (__nv_bfloat16*)pW3s, (float*)pa3, HIDF);
    // 6: layer 2 GEMM  [N,2048] -> [N,2048]
    bingemm_kernel<false><<<dim3(HIDF / 128, NROWS / 128), 256, DYN_SMEM>>>(
        (const __nv_bfloat16*)ph1, (const __nv_bfloat16*)pW2s,
        (const float*)pbe1, (const float*)pa2, b2, pw,
        (__nv_bfloat16*)ph2, (float*)pp2, nullptr, HIDF, HIDF);
    // 7: beta2
    redbeta_kernel<<<NROWS / 256, 256>>>((const float*)pp2, (float*)pbe2, HIDF / 128, 1.f / HIDF);
    // 8: layer 3 GEMM  [N,2048] -> [N,512], fp32 out
    bingemm_kernel<true><<<dim3(OUTF / 128, NROWS / 128), 256, DYN_SMEM>>>(
        (const __nv_bfloat16*)ph2, (const __nv_bfloat16*)pW3s,
        (const float*)pbe2, (const float*)pa3, b3, pw,
        nullptr, nullptr, out, OUTF, HIDF);
}